// round 1
// baseline (speedup 1.0000x reference)
#include <cuda_runtime.h>
#include <cuda_bf16.h>

#define NUM_SEGMENTS 2048
#define EPS 1e-6f
#define D_FEAT 64            // features per row (fixed by problem)
#define ROWS_PER_BLOCK 64    // reduce kernel: 1024 threads, half-warp per row

// Scratch (allocation-free rule: __device__ globals)
__device__ unsigned g_min_enc[NUM_SEGMENTS];
__device__ unsigned g_max_enc[NUM_SEGMENTS];
__device__ float    g_inv[NUM_SEGMENTS];   // 1/(mx-mn+eps)
__device__ float    g_b[NUM_SEGMENTS];     // -mn * inv

// Monotonic unsigned encoding of float (total order preserved)
__device__ __forceinline__ unsigned enc_f(float f) {
    unsigned u = __float_as_uint(f);
    return (u & 0x80000000u) ? ~u : (u | 0x80000000u);
}
__device__ __forceinline__ float dec_f(unsigned u) {
    u = (u & 0x80000000u) ? (u & 0x7FFFFFFFu) : ~u;
    return __uint_as_float(u);
}

// ---------------------------------------------------------------------------
// Kernel 1: init per-segment encoded min/max
// ---------------------------------------------------------------------------
__global__ void mmn_init_kernel() {
    int i = blockIdx.x * blockDim.x + threadIdx.x;
    if (i < NUM_SEGMENTS) {
        g_min_enc[i] = 0xFFFFFFFFu;  // encoded "+huge"
        g_max_enc[i] = 0x00000000u;  // encoded "-huge"
    }
}

// ---------------------------------------------------------------------------
// Kernel 2: per-segment min/max reduce.
// 1024 threads/block. Half-warp (16 lanes) per row, float4 per lane
// (16 lanes * 16B = 64 floats = one row). 64 rows per block, contiguous.
// Same-segment runs merged in smem before atomics (seg is sorted).
// ---------------------------------------------------------------------------
__global__ __launch_bounds__(1024, 2)
void mmn_reduce_kernel(const float4* __restrict__ x4,
                       const int* __restrict__ seg, int n_rows) {
    __shared__ float s_mn[ROWS_PER_BLOCK];
    __shared__ float s_mx[ROWS_PER_BLOCK];
    __shared__ int   s_sg[ROWS_PER_BLOCK];

    int tid  = threadIdx.x;
    int warp = tid >> 5;
    int lane = tid & 31;
    int row_in_blk = warp * 2 + (lane >> 4);
    int row = blockIdx.x * ROWS_PER_BLOCK + row_in_blk;

    int rows_here = n_rows - blockIdx.x * ROWS_PER_BLOCK;
    if (rows_here > ROWS_PER_BLOCK) rows_here = ROWS_PER_BLOCK;

    if (row < n_rows) {
        // row has D_FEAT=64 floats = 16 float4s; lane&15 picks one
        float4 v = __ldg(&x4[(long long)row * (D_FEAT / 4) + (lane & 15)]);
        float mn = fminf(fminf(v.x, v.y), fminf(v.z, v.w));
        float mx = fmaxf(fmaxf(v.x, v.y), fmaxf(v.z, v.w));
        // reduce across the 16-lane half-warp (xor 1,2,4,8 stays within half)
        #pragma unroll
        for (int m = 8; m >= 1; m >>= 1) {
            mn = fminf(mn, __shfl_xor_sync(0xFFFFFFFFu, mn, m));
            mx = fmaxf(mx, __shfl_xor_sync(0xFFFFFFFFu, mx, m));
        }
        if ((lane & 15) == 0) {
            s_mn[row_in_blk] = mn;
            s_mx[row_in_blk] = mx;
            s_sg[row_in_blk] = __ldg(&seg[row]);
        }
    }
    __syncthreads();

    // Merge runs of equal segment id, one leader thread per run issues atomics.
    int k = tid;
    if (k < rows_here) {
        int s = s_sg[k];
        bool leader = (k == 0) || (s_sg[k - 1] != s);
        if (leader) {
            float m = s_mn[k], M = s_mx[k];
            int j = k + 1;
            while (j < rows_here && s_sg[j] == s) {
                m = fminf(m, s_mn[j]);
                M = fmaxf(M, s_mx[j]);
                ++j;
            }
            atomicMin(&g_min_enc[s], enc_f(m));
            atomicMax(&g_max_enc[s], enc_f(M));
        }
    }
}

// ---------------------------------------------------------------------------
// Kernel 3: finalize per-segment (inv, b) so normalize is one FMA/elem
// ---------------------------------------------------------------------------
__global__ void mmn_finalize_kernel() {
    int s = blockIdx.x * blockDim.x + threadIdx.x;
    if (s < NUM_SEGMENTS) {
        float mn = dec_f(g_min_enc[s]);
        float mx = dec_f(g_max_enc[s]);
        float inv = 1.0f / (mx - mn + EPS);  // empty segs -> garbage, never read
        g_inv[s] = inv;
        g_b[s]   = -mn * inv;
    }
}

// ---------------------------------------------------------------------------
// Kernel 4: normalize. One float4 per thread; 16 consecutive threads share a
// row so the seg load broadcasts. Pure streaming: 16B in, 16B out, 1 FMA/elem.
// ---------------------------------------------------------------------------
__global__ __launch_bounds__(256)
void mmn_normalize_kernel(const float4* __restrict__ x4,
                          const int* __restrict__ seg,
                          float4* __restrict__ out4, long long n_f4) {
    long long i = (long long)blockIdx.x * blockDim.x + threadIdx.x;
    if (i < n_f4) {
        int row = (int)(i >> 4);  // 16 float4s per row (D=64)
        int s = __ldg(&seg[row]);
        float inv = g_inv[s];
        float b   = g_b[s];
        float4 v = __ldg(&x4[i]);
        float4 o;
        o.x = fmaf(v.x, inv, b);
        o.y = fmaf(v.y, inv, b);
        o.z = fmaf(v.z, inv, b);
        o.w = fmaf(v.w, inv, b);
        out4[i] = o;
    }
}

// ---------------------------------------------------------------------------
extern "C" void kernel_launch(void* const* d_in, const int* in_sizes, int n_in,
                              void* d_out, int out_size) {
    const float* x   = (const float*)d_in[0];
    const int*   seg = (const int*)d_in[1];
    float*       out = (float*)d_out;

    int n_rows = in_sizes[1];                       // N (seg element count)
    long long n_elems = (long long)in_sizes[0];     // N * 64
    long long n_f4 = n_elems / 4;

    // 1. init segment accumulators
    mmn_init_kernel<<<(NUM_SEGMENTS + 255) / 256, 256>>>();

    // 2. per-segment min/max
    int red_blocks = (n_rows + ROWS_PER_BLOCK - 1) / ROWS_PER_BLOCK;
    mmn_reduce_kernel<<<red_blocks, 1024>>>((const float4*)x, seg, n_rows);

    // 3. finalize (inv, b)
    mmn_finalize_kernel<<<(NUM_SEGMENTS + 255) / 256, 256>>>();

    // 4. normalize
    long long norm_blocks = (n_f4 + 255) / 256;
    mmn_normalize_kernel<<<(unsigned)norm_blocks, 256>>>(
        (const float4*)x, seg, (float4*)out, n_f4);
}

// round 2
// speedup vs baseline: 1.9337x; 1.9337x over previous
#include <cuda_runtime.h>
#include <cuda_bf16.h>
#include <math_constants.h>

#define NUM_SEGMENTS 2048
#define EPS 1e-6f
#define D_FEAT 64             // floats per row
#define F4_PER_ROW 16         // float4 per row
#define ROWS_PER_WARP 4       // reduce kernel: 8 lanes per row, 2 float4/lane
#define ROWS_PER_BLOCK 128    // 32 warps * 4 rows

// Scratch (allocation-free rule: __device__ globals)
__device__ unsigned g_min_enc[NUM_SEGMENTS];
__device__ unsigned g_max_enc[NUM_SEGMENTS];
__device__ float    g_inv[NUM_SEGMENTS];   // 1/(mx-mn+eps)
__device__ float    g_b[NUM_SEGMENTS];     // -mn * inv

// Monotonic unsigned encoding of float (total order preserved)
__device__ __forceinline__ unsigned enc_f(float f) {
    unsigned u = __float_as_uint(f);
    return (u & 0x80000000u) ? ~u : (u | 0x80000000u);
}
__device__ __forceinline__ float dec_f(unsigned u) {
    u = (u & 0x80000000u) ? (u & 0x7FFFFFFFu) : ~u;
    return __uint_as_float(u);
}

// ---------------------------------------------------------------------------
// Kernel 1: init per-segment encoded min/max
// ---------------------------------------------------------------------------
__global__ void mmn_init_kernel() {
    int i = blockIdx.x * blockDim.x + threadIdx.x;
    if (i < NUM_SEGMENTS) {
        g_min_enc[i] = 0xFFFFFFFFu;  // encoded "+huge"
        g_max_enc[i] = 0x00000000u;  // encoded "-huge"
    }
}

// ---------------------------------------------------------------------------
// Kernel 2: per-segment min/max reduce.
// Warp handles 4 consecutive rows: 8 lanes per row, each lane loads 2 float4
// (MLP=2, 512B contiguous per row-group). Shfl-only merge within the warp
// (no smem, no __syncthreads, no serial scans). First-occurrence leader per
// segment within the warp issues the global atomics.
// ---------------------------------------------------------------------------
__global__ __launch_bounds__(1024)
void mmn_reduce_kernel(const float4* __restrict__ x4,
                       const int* __restrict__ seg, int n_rows) {
    int warp = threadIdx.x >> 5;
    int lane = threadIdx.x & 31;
    int l8   = lane & 7;                  // lane within 8-lane row group
    int sub  = lane >> 3;                 // which of 4 rows in this warp
    int row  = blockIdx.x * ROWS_PER_BLOCK + warp * ROWS_PER_WARP + sub;

    float mn = CUDART_INF_F;
    float mx = -CUDART_INF_F;
    int   sg = -1;

    if (row < n_rows) {
        long long base = (long long)row * F4_PER_ROW + l8;
        float4 a = __ldcs(&x4[base]);
        float4 b = __ldcs(&x4[base + 8]);
        mn = fminf(fminf(fminf(a.x, a.y), fminf(a.z, a.w)),
                   fminf(fminf(b.x, b.y), fminf(b.z, b.w)));
        mx = fmaxf(fmaxf(fmaxf(a.x, a.y), fmaxf(a.z, a.w)),
                   fmaxf(fmaxf(b.x, b.y), fmaxf(b.z, b.w)));
        if (l8 == 0) sg = __ldg(&seg[row]);
    }

    // Reduce across the 8-lane row group (xor 4,2,1 stays within group)
    #pragma unroll
    for (int m = 4; m >= 1; m >>= 1) {
        mn = fminf(mn, __shfl_xor_sync(0xFFFFFFFFu, mn, m));
        mx = fmaxf(mx, __shfl_xor_sync(0xFFFFFFFFu, mx, m));
    }

    // Broadcast the 4 row results across the warp and merge equal segments.
    int   sg0 = __shfl_sync(0xFFFFFFFFu, sg, 0);
    int   sg1 = __shfl_sync(0xFFFFFFFFu, sg, 8);
    int   sg2 = __shfl_sync(0xFFFFFFFFu, sg, 16);
    int   sg3 = __shfl_sync(0xFFFFFFFFu, sg, 24);
    float mn0 = __shfl_sync(0xFFFFFFFFu, mn, 0);
    float mn1 = __shfl_sync(0xFFFFFFFFu, mn, 8);
    float mn2 = __shfl_sync(0xFFFFFFFFu, mn, 16);
    float mn3 = __shfl_sync(0xFFFFFFFFu, mn, 24);
    float mx0 = __shfl_sync(0xFFFFFFFFu, mx, 0);
    float mx1 = __shfl_sync(0xFFFFFFFFu, mx, 8);
    float mx2 = __shfl_sync(0xFFFFFFFFu, mx, 16);
    float mx3 = __shfl_sync(0xFFFFFFFFu, mx, 24);

    if (l8 == 0 && sg >= 0) {
        int   sgs[4] = {sg0, sg1, sg2, sg3};
        float mns[4] = {mn0, mn1, mn2, mn3};
        float mxs[4] = {mx0, mx1, mx2, mx3};
        bool first = true;
        float m = mn, M = mx;
        #pragma unroll
        for (int j = 0; j < 4; ++j) {
            if (j < sub && sgs[j] == sg) first = false;
            if (j > sub && sgs[j] == sg) {
                m = fminf(m, mns[j]);
                M = fmaxf(M, mxs[j]);
            }
        }
        if (first) {
            atomicMin(&g_min_enc[sg], enc_f(m));
            atomicMax(&g_max_enc[sg], enc_f(M));
        }
    }
}

// ---------------------------------------------------------------------------
// Kernel 3: finalize per-segment (inv, b) so normalize is one FMA/elem
// ---------------------------------------------------------------------------
__global__ void mmn_finalize_kernel() {
    int s = blockIdx.x * blockDim.x + threadIdx.x;
    if (s < NUM_SEGMENTS) {
        float mn = dec_f(g_min_enc[s]);
        float mx = dec_f(g_max_enc[s]);
        float inv = 1.0f / (mx - mn + EPS);  // empty segs -> garbage, never read
        g_inv[s] = inv;
        g_b[s]   = -mn * inv;
    }
}

// ---------------------------------------------------------------------------
// Kernel 4: normalize. Each thread handles 2 consecutive float4 (32B) within
// one row -> single seg lookup, MLP=2. Streaming loads/stores (evict-first).
// ---------------------------------------------------------------------------
__global__ __launch_bounds__(256)
void mmn_normalize_kernel(const float4* __restrict__ x4,
                          const int* __restrict__ seg,
                          float4* __restrict__ out4, int n_rows) {
    long long p = (long long)blockIdx.x * blockDim.x + threadIdx.x; // pair idx
    int row = (int)(p >> 3);   // 8 pairs per row
    if (row < n_rows) {
        int s = __ldg(&seg[row]);
        float inv = g_inv[s];
        float b   = g_b[s];
        long long base = ((long long)row << 4) + ((p & 7) << 1);
        float4 v0 = __ldcs(&x4[base]);
        float4 v1 = __ldcs(&x4[base + 1]);
        float4 o0, o1;
        o0.x = fmaf(v0.x, inv, b); o0.y = fmaf(v0.y, inv, b);
        o0.z = fmaf(v0.z, inv, b); o0.w = fmaf(v0.w, inv, b);
        o1.x = fmaf(v1.x, inv, b); o1.y = fmaf(v1.y, inv, b);
        o1.z = fmaf(v1.z, inv, b); o1.w = fmaf(v1.w, inv, b);
        __stcs(&out4[base], o0);
        __stcs(&out4[base + 1], o1);
    }
}

// ---------------------------------------------------------------------------
extern "C" void kernel_launch(void* const* d_in, const int* in_sizes, int n_in,
                              void* d_out, int out_size) {
    const float* x   = (const float*)d_in[0];
    const int*   seg = (const int*)d_in[1];
    float*       out = (float*)d_out;

    int n_rows = in_sizes[1];   // N (seg element count)

    // 1. init segment accumulators
    mmn_init_kernel<<<(NUM_SEGMENTS + 255) / 256, 256>>>();

    // 2. per-segment min/max
    int red_blocks = (n_rows + ROWS_PER_BLOCK - 1) / ROWS_PER_BLOCK;
    mmn_reduce_kernel<<<red_blocks, 1024>>>((const float4*)x, seg, n_rows);

    // 3. finalize (inv, b)
    mmn_finalize_kernel<<<(NUM_SEGMENTS + 255) / 256, 256>>>();

    // 4. normalize: n_rows * 8 pair-threads
    long long n_pairs = (long long)n_rows * 8;
    int norm_blocks = (int)((n_pairs + 255) / 256);
    mmn_normalize_kernel<<<norm_blocks, 256>>>(
        (const float4*)x, seg, (float4*)out, n_rows);
}

// round 3
// speedup vs baseline: 2.7830x; 1.4392x over previous
#include <cuda_runtime.h>
#include <cuda_bf16.h>
#include <math_constants.h>

#define NUM_SEGMENTS 2048
#define EPS 1e-6f
#define F4_PER_ROW 16          // 64 floats per row = 16 float4
#define FUSED_THREADS 512      // 4 blocks/SM -> L2-resident working set

// seg_start[s] = first row of segment s; seg_start[NUM_SEGMENTS] = n_rows
__device__ int g_seg_start[NUM_SEGMENTS + 1];

// ---------------------------------------------------------------------------
// Kernel 1: segment boundaries from sorted seg array.
// Thread i fills seg_start[s] = i for all s in (seg[i-1], seg[i]].
// ---------------------------------------------------------------------------
__global__ void mmn_bounds_kernel(const int* __restrict__ seg, int n_rows) {
    int i = blockIdx.x * blockDim.x + threadIdx.x;
    if (i >= n_rows) return;
    int s_cur = __ldg(&seg[i]);
    int s_prev = (i == 0) ? -1 : __ldg(&seg[i - 1]);
    for (int s = s_prev + 1; s <= s_cur; ++s)
        g_seg_start[s] = i;
    if (i == n_rows - 1) {
        for (int s = s_cur + 1; s <= NUM_SEGMENTS; ++s)
            g_seg_start[s] = n_rows;
    }
}

// ---------------------------------------------------------------------------
// Kernel 2: fused per-segment min/max + normalize. One block per segment.
// Pass A: stream the segment's rows from DRAM, block-reduce min/max.
// Pass B: re-read the same rows (L2-resident) and write normalized output
// with evict-first stores. No atomics anywhere.
// ---------------------------------------------------------------------------
__global__ __launch_bounds__(FUSED_THREADS)
void mmn_fused_kernel(const float4* __restrict__ x4,
                      float4* __restrict__ out4) {
    __shared__ float s_mn[FUSED_THREADS / 32];
    __shared__ float s_mx[FUSED_THREADS / 32];
    __shared__ float s_inv, s_b;

    int s  = blockIdx.x;
    int r0 = g_seg_start[s];
    int r1 = g_seg_start[s + 1];
    if (r0 >= r1) return;                  // empty segment

    long long f0 = (long long)r0 * F4_PER_ROW;
    long long f1 = (long long)r1 * F4_PER_ROW;
    int tid  = threadIdx.x;
    int warp = tid >> 5;
    int lane = tid & 31;

    // ---- Pass A: block min/max over [f0, f1) ----
    float mn = CUDART_INF_F, mx = -CUDART_INF_F;
    #pragma unroll 4
    for (long long i = f0 + tid; i < f1; i += FUSED_THREADS) {
        float4 v = __ldg(&x4[i]);          // default policy: keep in L2
        mn = fminf(mn, fminf(fminf(v.x, v.y), fminf(v.z, v.w)));
        mx = fmaxf(mx, fmaxf(fmaxf(v.x, v.y), fmaxf(v.z, v.w)));
    }
    #pragma unroll
    for (int m = 16; m >= 1; m >>= 1) {
        mn = fminf(mn, __shfl_xor_sync(0xFFFFFFFFu, mn, m));
        mx = fmaxf(mx, __shfl_xor_sync(0xFFFFFFFFu, mx, m));
    }
    if (lane == 0) { s_mn[warp] = mn; s_mx[warp] = mx; }
    __syncthreads();
    if (warp == 0) {
        const int NW = FUSED_THREADS / 32;
        mn = (lane < NW) ? s_mn[lane] : CUDART_INF_F;
        mx = (lane < NW) ? s_mx[lane] : -CUDART_INF_F;
        #pragma unroll
        for (int m = NW / 2; m >= 1; m >>= 1) {
            mn = fminf(mn, __shfl_xor_sync(0xFFFFFFFFu, mn, m));
            mx = fmaxf(mx, __shfl_xor_sync(0xFFFFFFFFu, mx, m));
        }
        if (lane == 0) {
            float inv = 1.0f / (mx - mn + EPS);
            s_inv = inv;
            s_b   = -mn * inv;
        }
    }
    __syncthreads();
    float inv = s_inv;
    float b   = s_b;

    // ---- Pass B: normalize; reads hit L2, stores evict-first ----
    #pragma unroll 4
    for (long long i = f0 + tid; i < f1; i += FUSED_THREADS) {
        float4 v = __ldg(&x4[i]);
        float4 o;
        o.x = fmaf(v.x, inv, b);
        o.y = fmaf(v.y, inv, b);
        o.z = fmaf(v.z, inv, b);
        o.w = fmaf(v.w, inv, b);
        __stcs(&out4[i], o);
    }
}

// ---------------------------------------------------------------------------
extern "C" void kernel_launch(void* const* d_in, const int* in_sizes, int n_in,
                              void* d_out, int out_size) {
    const float* x   = (const float*)d_in[0];
    const int*   seg = (const int*)d_in[1];
    float*       out = (float*)d_out;

    int n_rows = in_sizes[1];   // N

    // 1. segment boundaries
    mmn_bounds_kernel<<<(n_rows + 255) / 256, 256>>>(seg, n_rows);

    // 2. fused min/max + normalize, one block per segment
    mmn_fused_kernel<<<NUM_SEGMENTS, FUSED_THREADS>>>(
        (const float4*)x, (float4*)out);
}

// round 4
// speedup vs baseline: 3.2736x; 1.1763x over previous
#include <cuda_runtime.h>
#include <cuda_bf16.h>
#include <math_constants.h>

#define NUM_SEGMENTS 2048
#define EPS 1e-6f
#define F4_PER_ROW 16           // 64 floats per row = 16 float4
#define FUSED_THREADS 1024      // warp cap -> max 2 blocks/SM -> 37MB L2 set

// seg_start[s] = first row of segment s; seg_start[NUM_SEGMENTS] = n_rows
__device__ int g_seg_start[NUM_SEGMENTS + 1];

// ---------------------------------------------------------------------------
// Kernel 1: segment boundaries from sorted seg array.
// ---------------------------------------------------------------------------
__global__ void mmn_bounds_kernel(const int* __restrict__ seg, int n_rows) {
    int i = blockIdx.x * blockDim.x + threadIdx.x;
    if (i >= n_rows) return;
    int s_cur = __ldg(&seg[i]);
    int s_prev = (i == 0) ? -1 : __ldg(&seg[i - 1]);
    for (int s = s_prev + 1; s <= s_cur; ++s)
        g_seg_start[s] = i;
    if (i == n_rows - 1) {
        for (int s = s_cur + 1; s <= NUM_SEGMENTS; ++s)
            g_seg_start[s] = n_rows;
    }
}

// ---------------------------------------------------------------------------
// Kernel 2: fused per-segment min/max + normalize. One block per segment.
// Pass A: stream rows from DRAM (default policy -> lines land in L2),
//         block-reduce min/max.
// Pass B: re-read same rows with evict-first (L2 hit, then free the line),
//         write normalized output evict-first. No atomics.
// 2 blocks/SM max => concurrent working set ~37MB << 126MB L2.
// ---------------------------------------------------------------------------
__global__ __launch_bounds__(FUSED_THREADS)
void mmn_fused_kernel(const float4* __restrict__ x4,
                      float4* __restrict__ out4) {
    __shared__ float s_mn[FUSED_THREADS / 32];
    __shared__ float s_mx[FUSED_THREADS / 32];
    __shared__ float s_inv, s_b;

    int s  = blockIdx.x;
    int r0 = g_seg_start[s];
    int r1 = g_seg_start[s + 1];
    if (r0 >= r1) return;                  // empty segment

    long long f0 = (long long)r0 * F4_PER_ROW;
    long long f1 = (long long)r1 * F4_PER_ROW;
    int tid  = threadIdx.x;
    int warp = tid >> 5;
    int lane = tid & 31;

    // ---- Pass A: block min/max over [f0, f1) ----
    float mn = CUDART_INF_F, mx = -CUDART_INF_F;
    #pragma unroll 4
    for (long long i = f0 + tid; i < f1; i += FUSED_THREADS) {
        float4 v = __ldg(&x4[i]);          // populate L2
        mn = fminf(mn, fminf(fminf(v.x, v.y), fminf(v.z, v.w)));
        mx = fmaxf(mx, fmaxf(fmaxf(v.x, v.y), fmaxf(v.z, v.w)));
    }
    #pragma unroll
    for (int m = 16; m >= 1; m >>= 1) {
        mn = fminf(mn, __shfl_xor_sync(0xFFFFFFFFu, mn, m));
        mx = fmaxf(mx, __shfl_xor_sync(0xFFFFFFFFu, mx, m));
    }
    if (lane == 0) { s_mn[warp] = mn; s_mx[warp] = mx; }
    __syncthreads();
    if (warp == 0) {
        const int NW = FUSED_THREADS / 32;
        mn = (lane < NW) ? s_mn[lane] : CUDART_INF_F;
        mx = (lane < NW) ? s_mx[lane] : -CUDART_INF_F;
        #pragma unroll
        for (int m = NW / 2; m >= 1; m >>= 1) {
            mn = fminf(mn, __shfl_xor_sync(0xFFFFFFFFu, mn, m));
            mx = fmaxf(mx, __shfl_xor_sync(0xFFFFFFFFu, mx, m));
        }
        if (lane == 0) {
            float inv = 1.0f / (mx - mn + EPS);
            s_inv = inv;
            s_b   = -mn * inv;
        }
    }
    __syncthreads();
    float inv = s_inv;
    float b   = s_b;

    // ---- Pass B: L2-hit reads (evict after use), evict-first stores ----
    #pragma unroll 4
    for (long long i = f0 + tid; i < f1; i += FUSED_THREADS) {
        float4 v = __ldcs(&x4[i]);         // last use: free the L2 line
        float4 o;
        o.x = fmaf(v.x, inv, b);
        o.y = fmaf(v.y, inv, b);
        o.z = fmaf(v.z, inv, b);
        o.w = fmaf(v.w, inv, b);
        __stcs(&out4[i], o);
    }
}

// ---------------------------------------------------------------------------
extern "C" void kernel_launch(void* const* d_in, const int* in_sizes, int n_in,
                              void* d_out, int out_size) {
    const float* x   = (const float*)d_in[0];
    const int*   seg = (const int*)d_in[1];
    float*       out = (float*)d_out;

    int n_rows = in_sizes[1];   // N

    // 1. segment boundaries
    mmn_bounds_kernel<<<(n_rows + 255) / 256, 256>>>(seg, n_rows);

    // 2. fused min/max + normalize, one block per segment
    mmn_fused_kernel<<<NUM_SEGMENTS, FUSED_THREADS>>>(
        (const float4*)x, (float4*)out);
}